// round 6
// baseline (speedup 1.0000x reference)
#include <cuda_runtime.h>
#include <cuda_bf16.h>
#include <math.h>

// Problem dims
#define T_STEPS 256
#define OBS     512
#define ACT     32
#define HID     1024
#define MSG     128
#define PE      128
#define GATES   512          // 4*PE
#define IN_DIM  33           // 1 + ACT
#define INV_SC  0.08838834764831843f   // 1/sqrt(128)

// LSTM smem cache: number of float4 e-slices of W_hh kept in shared memory (of 32)
#define EC4 27

// ---------------- device scratch (static, no allocation) ----------------
__device__ float  g_XN [T_STEPS * OBS];        // normalized obs [t][j]
__device__ float  g_SH [T_STEPS * GATES];      // per-step gate constant [t][r]
__device__ float  g_W0 [GATES];                // W_ih[:,0]
__device__ float4 g_W4 [32 * GATES];           // W_hh e-sliced: [e][r] = W_hh[r][4e..4e+3]
__device__ float  g_q  [HID * MSG];            // q = pos @ Wq^T + bq, [i][m]
__device__ float  g_QWT[PE * HID];             // inv * (q @ Wk), TRANSPOSED: [p][i]
__device__ float  g_qbs[HID];                  // inv * (q . bk)
__device__ float  g_HT [T_STEPS * PE * OBS];   // h storage TRANSPOSED: [t][p][j]  (64 MB)

// ---------------- fast-but-accurate activations ----------------
__device__ __forceinline__ float sig_f(float x) {
    // 1/(1+e^-x); __expf rel err ~1e-7; inf-safe at both ends
    return __fdividef(1.f, 1.f + __expf(-x));
}
__device__ __forceinline__ float tanh_f(float x) {
    float ax = fabsf(x);
    float e  = __expf(-2.f * ax);       // in (0,1], never overflows
    float r  = __fdividef(1.f - e, 1.f + e);
    return copysignf(r, x);
}

// ======================================================================
// K0: normalized obs + per-step gate constants
// grid(T_STEPS), block(512)
// ======================================================================
__global__ void k_pre1(const float* __restrict__ obs,
                       const float* __restrict__ act,
                       const float* __restrict__ shift,
                       const float* __restrict__ scale,
                       const float* __restrict__ W_ih,
                       const float* __restrict__ b_ih,
                       const float* __restrict__ b_hh) {
    __shared__ float actS[ACT];
    int t = blockIdx.x;
    int r = threadIdx.x;            // doubles as j for XN and r for SH
    if (r < ACT) actS[r] = act[t * ACT + r];
    __syncthreads();

    // XN
    g_XN[t * OBS + r] = (obs[t * OBS + r] - shift[r]) / (scale[r] + 1e-8f);

    // SH
    float sh = b_ih[r] + b_hh[r];
    const float* wrow = W_ih + r * IN_DIM + 1;
#pragma unroll 8
    for (int a = 0; a < ACT; a++) sh = fmaf(wrow[a], actS[a], sh);
    g_SH[t * GATES + r] = sh;
}

// ======================================================================
// K0b: W_hh e-slice layout + W0
// grid(32), block(512)
// ======================================================================
__global__ void k_pre2(const float* __restrict__ W_hh,
                       const float* __restrict__ W_ih) {
    int e = blockIdx.x;
    int r = threadIdx.x;
    const float* row = W_hh + r * PE + 4 * e;
    g_W4[e * GATES + r] = make_float4(row[0], row[1], row[2], row[3]);
    if (e == 0) g_W0[r] = W_ih[r * IN_DIM];
}

// ======================================================================
// K1: q = pos @ Wq^T + bq
// grid(32) i-tiles of 32, block(256), dyn smem = 16KB posS + 64KB WqT
// ======================================================================
__global__ void __launch_bounds__(256) k_q(const float* __restrict__ pos,
                                           const float* __restrict__ Wq,
                                           const float* __restrict__ bq) {
    extern __shared__ float sm[];
    float* posS = sm;            // [32][128]
    float* WqT  = sm + 32 * PE;  // [e][m]
    int i0 = blockIdx.x * 32;
    int tid = threadIdx.x;

    for (int idx = tid; idx < 32 * PE; idx += 256) posS[idx] = pos[i0 * PE + idx];
    for (int idx = tid; idx < MSG * PE; idx += 256) {
        int m = idx >> 7, e = idx & 127;
        WqT[e * MSG + m] = Wq[idx];
    }
    __syncthreads();

    int m  = tid & 127;
    int ih = tid >> 7;
    float bqm = bq[m];
#pragma unroll
    for (int s8 = 0; s8 < 16; s8++) {
        int isub = ih * 16 + s8;
        float acc = bqm;
#pragma unroll 8
        for (int e = 0; e < PE; e++)
            acc = fmaf(posS[isub * PE + e], WqT[e * MSG + m], acc);
        g_q[(i0 + isub) * MSG + m] = acc;
    }
}

// ======================================================================
// K2: QWT[p][i] = inv * (q @ Wk)[i][p] ; qbs[i] = inv * q[i].bk
// grid(32) i-tiles of 32, block(256), dyn smem = 16KB qS + 64KB WkS
// ======================================================================
__global__ void __launch_bounds__(256) k_qw(const float* __restrict__ Wk,
                                            const float* __restrict__ bk) {
    extern __shared__ float sm[];
    float* qS  = sm;             // [32][128]
    float* WkS = sm + 32 * MSG;  // [m][p]
    int i0 = blockIdx.x * 32;
    int tid = threadIdx.x;

    for (int idx = tid; idx < 32 * MSG; idx += 256) qS[idx] = g_q[i0 * MSG + idx];
    for (int idx = tid; idx < MSG * PE; idx += 256) WkS[idx] = Wk[idx];
    __syncthreads();

    int p  = tid & 127;
    int ih = tid >> 7;
#pragma unroll
    for (int s8 = 0; s8 < 16; s8++) {
        int isub = ih * 16 + s8;
        float acc = 0.f;
#pragma unroll 8
        for (int m = 0; m < MSG; m++)
            acc = fmaf(qS[isub * MSG + m], WkS[m * PE + p], acc);
        g_QWT[p * HID + i0 + isub] = acc * INV_SC;
    }
    if (tid < 32) {
        float acc = 0.f;
#pragma unroll 8
        for (int m = 0; m < MSG; m++) acc = fmaf(qS[tid * MSG + m], bk[m], acc);
        g_qbs[i0 + tid] = acc * INV_SC;
    }
}

// ======================================================================
// K3: LSTM over 256 steps. 128 CTAs x 4 chains, 128 threads (thread = unit m).
// dyn smem: EC4 float4 e-slices of W_hh (216KB) + h state (2KB) = 223232 B
// ======================================================================
__global__ void __launch_bounds__(128, 1) k_lstm() {
    extern __shared__ float sm[];
    float4* Ws = reinterpret_cast<float4*>(sm);   // [EC4][512]
    float*  hs = sm + EC4 * GATES * 4;            // [4][128]

    int m  = threadIdx.x;
    int j0 = blockIdx.x * 4;

    for (int idx = m; idx < EC4 * GATES; idx += 128) Ws[idx] = g_W4[idx];
#pragma unroll
    for (int ch = 0; ch < 4; ch++) hs[ch * PE + m] = 0.f;

    float cst[4] = {0.f, 0.f, 0.f, 0.f};
    float w00 = g_W0[m], w01 = g_W0[m + 128], w02 = g_W0[m + 256], w03 = g_W0[m + 384];
    __syncthreads();

    for (int t = 0; t < T_STEPS; t++) {
        // prefetch step constants (consumed after the long dot loop)
        float sh0 = g_SH[t * GATES + m];
        float sh1 = g_SH[t * GATES + m + 128];
        float sh2 = g_SH[t * GATES + m + 256];
        float sh3 = g_SH[t * GATES + m + 384];
        float xn[4];
#pragma unroll
        for (int ch = 0; ch < 4; ch++) xn[ch] = g_XN[t * OBS + j0 + ch];

        float acc[4][4];
#pragma unroll
        for (int r = 0; r < 4; r++)
#pragma unroll
            for (int ch = 0; ch < 4; ch++) acc[r][ch] = 0.f;

        // h . W_hh^T over p, float4-sliced: smem-cached slices
#pragma unroll 3
        for (int e = 0; e < EC4; e++) {
            float4 wa = Ws[e * GATES + m];
            float4 wb = Ws[e * GATES + m + 128];
            float4 wc = Ws[e * GATES + m + 256];
            float4 wd = Ws[e * GATES + m + 384];
#pragma unroll
            for (int ch = 0; ch < 4; ch++) {
                float4 h4 = reinterpret_cast<const float4*>(hs + ch * PE)[e];
                acc[0][ch] = fmaf(wa.x, h4.x, fmaf(wa.y, h4.y, fmaf(wa.z, h4.z, fmaf(wa.w, h4.w, acc[0][ch]))));
                acc[1][ch] = fmaf(wb.x, h4.x, fmaf(wb.y, h4.y, fmaf(wb.z, h4.z, fmaf(wb.w, h4.w, acc[1][ch]))));
                acc[2][ch] = fmaf(wc.x, h4.x, fmaf(wc.y, h4.y, fmaf(wc.z, h4.z, fmaf(wc.w, h4.w, acc[2][ch]))));
                acc[3][ch] = fmaf(wd.x, h4.x, fmaf(wd.y, h4.y, fmaf(wd.z, h4.z, fmaf(wd.w, h4.w, acc[3][ch]))));
            }
        }
        // remaining slices from global (L2-resident)
#pragma unroll
        for (int e = EC4; e < 32; e++) {
            const float4* G = &g_W4[e * GATES];
            float4 wa = G[m];
            float4 wb = G[m + 128];
            float4 wc = G[m + 256];
            float4 wd = G[m + 384];
#pragma unroll
            for (int ch = 0; ch < 4; ch++) {
                float4 h4 = reinterpret_cast<const float4*>(hs + ch * PE)[e];
                acc[0][ch] = fmaf(wa.x, h4.x, fmaf(wa.y, h4.y, fmaf(wa.z, h4.z, fmaf(wa.w, h4.w, acc[0][ch]))));
                acc[1][ch] = fmaf(wb.x, h4.x, fmaf(wb.y, h4.y, fmaf(wb.z, h4.z, fmaf(wb.w, h4.w, acc[1][ch]))));
                acc[2][ch] = fmaf(wc.x, h4.x, fmaf(wc.y, h4.y, fmaf(wc.z, h4.z, fmaf(wc.w, h4.w, acc[2][ch]))));
                acc[3][ch] = fmaf(wd.x, h4.x, fmaf(wd.y, h4.y, fmaf(wd.z, h4.z, fmaf(wd.w, h4.w, acc[3][ch]))));
            }
        }

        __syncthreads();   // all reads of hs done before overwrite

        float hv[4];
#pragma unroll
        for (int ch = 0; ch < 4; ch++) {
            float gi = acc[0][ch] + sh0 + w00 * xn[ch];
            float gf = acc[1][ch] + sh1 + w01 * xn[ch];
            float gg = acc[2][ch] + sh2 + w02 * xn[ch];
            float go = acc[3][ch] + sh3 + w03 * xn[ch];
            float ig = sig_f(gi);
            float fg = sig_f(gf);
            float g  = tanh_f(gg);
            float og = sig_f(go);
            float cn = fmaf(fg, cst[ch], ig * g);
            cst[ch] = cn;
            hv[ch]  = og * tanh_f(cn);
            hs[ch * PE + m] = hv[ch];
        }
        // transposed store for the attention GEMM: [t][p=m][j0..j0+3]
        *reinterpret_cast<float4*>(&g_HT[(t * PE + m) * OBS + j0]) =
            make_float4(hv[0], hv[1], hv[2], hv[3]);

        __syncthreads();   // writes visible before next step's reads
    }
}

// ======================================================================
// K4: attention readout.
// grid(8 i-tiles, 256 t), block(256). dyn smem: As 64KB + Bs 64KB + xn 2KB.
// out[t][i] = tanh( sum_j tanh(QWT[:,i].H_t[:,j] + qbs[i]) * xn[t][j] )
// ======================================================================
__global__ void __launch_bounds__(256, 1) k_attn(float* __restrict__ out) {
    extern __shared__ float sm[];
    float* As  = sm;               // [p][i_local] 128x128
    float* Bs  = sm + 16384;       // [p][j_local] 128x128
    float* xnS = sm + 32768;       // [512]

    int t   = blockIdx.y;
    int bx  = blockIdx.x;
    int tid = threadIdx.x;
    int tx  = tid & 15;            // j-group
    int ty  = tid >> 4;            // i-group

    // As: coalesced copy, already transposed in global
    for (int idx = tid; idx < 4096; idx += 256) {
        int p = idx >> 5, c4 = idx & 31;
        reinterpret_cast<float4*>(As)[p * 32 + c4] =
            reinterpret_cast<const float4*>(g_QWT + p * HID + bx * 128)[c4];
    }
    for (int idx = tid; idx < OBS; idx += 256) xnS[idx] = g_XN[t * OBS + idx];

    float qb[8];
#pragma unroll
    for (int ii = 0; ii < 8; ii++) qb[ii] = g_qbs[bx * 128 + ty * 8 + ii];

    float outa[8];
#pragma unroll
    for (int ii = 0; ii < 8; ii++) outa[ii] = 0.f;

    const float* Hbase = g_HT + (size_t)t * PE * OBS;

    for (int jt = 0; jt < 4; jt++) {
        __syncthreads();           // previous k-loop done before Bs overwrite
        for (int idx = tid; idx < 4096; idx += 256) {
            int p = idx >> 5, c4 = idx & 31;
            reinterpret_cast<float4*>(Bs)[p * 32 + c4] =
                reinterpret_cast<const float4*>(Hbase + p * OBS + jt * 128)[c4];
        }
        __syncthreads();

        float acc[8][8];
#pragma unroll
        for (int ii = 0; ii < 8; ii++)
#pragma unroll
            for (int jj = 0; jj < 8; jj++) acc[ii][jj] = 0.f;

#pragma unroll 4
        for (int p = 0; p < PE; p++) {
            float4 a0 = *reinterpret_cast<const float4*>(As + p * 128 + ty * 8);
            float4 a1 = *reinterpret_cast<const float4*>(As + p * 128 + ty * 8 + 4);
            float4 b0 = *reinterpret_cast<const float4*>(Bs + p * 128 + tx * 8);
            float4 b1 = *reinterpret_cast<const float4*>(Bs + p * 128 + tx * 8 + 4);
            float ar[8] = {a0.x, a0.y, a0.z, a0.w, a1.x, a1.y, a1.z, a1.w};
            float br[8] = {b0.x, b0.y, b0.z, b0.w, b1.x, b1.y, b1.z, b1.w};
#pragma unroll
            for (int ii = 0; ii < 8; ii++)
#pragma unroll
                for (int jj = 0; jj < 8; jj++)
                    acc[ii][jj] = fmaf(ar[ii], br[jj], acc[ii][jj]);
        }

        float xr[8];
#pragma unroll
        for (int jj = 0; jj < 8; jj++) xr[jj] = xnS[jt * 128 + tx * 8 + jj];
#pragma unroll
        for (int ii = 0; ii < 8; ii++)
#pragma unroll
            for (int jj = 0; jj < 8; jj++)
                outa[ii] = fmaf(tanh_f(acc[ii][jj] + qb[ii]), xr[jj], outa[ii]);
    }

    __syncthreads();
    // cross-tx reduction via smem (reuse As)
#pragma unroll
    for (int ii = 0; ii < 8; ii++) As[(ty * 8 + ii) * 16 + tx] = outa[ii];
    __syncthreads();

    if (tid < 128) {
        float s = 0.f;
#pragma unroll
        for (int q = 0; q < 16; q++) s += As[tid * 16 + q];
        out[t * HID + bx * 128 + tid] = tanh_f(s);
    }
}

// ======================================================================
// launcher
// ======================================================================
extern "C" void kernel_launch(void* const* d_in, const int* in_sizes, int n_in,
                              void* d_out, int out_size) {
    const float* obs    = (const float*)d_in[0];   // (256,512)
    const float* pact   = (const float*)d_in[1];   // (256,32)
    const float* shift  = (const float*)d_in[2];   // (512,)
    const float* scale  = (const float*)d_in[3];   // (512,)
    const float* pos    = (const float*)d_in[4];   // (1024,128)
    const float* W_ih   = (const float*)d_in[5];   // (512,33)
    const float* b_ih   = (const float*)d_in[6];   // (512,)
    const float* W_hh   = (const float*)d_in[7];   // (512,128)
    const float* b_hh   = (const float*)d_in[8];   // (512,)
    const float* Wq     = (const float*)d_in[9];   // (128,128)
    const float* bq     = (const float*)d_in[10];  // (128,)
    const float* Wk     = (const float*)d_in[11];  // (128,128)
    const float* bk     = (const float*)d_in[12];  // (128,)
    float* out = (float*)d_out;                    // (256,1024)

    // opt into >48KB dynamic smem (persistent attrs; redundant calls are harmless)
    cudaFuncSetAttribute(k_q,    cudaFuncAttributeMaxDynamicSharedMemorySize, 81920);
    cudaFuncSetAttribute(k_qw,   cudaFuncAttributeMaxDynamicSharedMemorySize, 81920);
    cudaFuncSetAttribute(k_lstm, cudaFuncAttributeMaxDynamicSharedMemorySize, 223232);
    cudaFuncSetAttribute(k_attn, cudaFuncAttributeMaxDynamicSharedMemorySize, 133120);

    k_pre1<<<T_STEPS, 512>>>(obs, pact, shift, scale, W_ih, b_ih, b_hh);
    k_pre2<<<32, 512>>>(W_hh, W_ih);
    k_q  <<<32, 256, 81920>>>(pos, Wq, bq);
    k_qw <<<32, 256, 81920>>>(Wk, bk);
    k_lstm<<<128, 128, 223232>>>();
    k_attn<<<dim3(8, T_STEPS), 256, 133120>>>(out);
}

// round 11
// speedup vs baseline: 1.0932x; 1.0932x over previous
#include <cuda_runtime.h>
#include <cuda_bf16.h>
#include <cstdint>
#include <math.h>

// Problem dims
#define T_STEPS 256
#define OBS     512
#define ACT     32
#define HID     1024
#define MSG     128
#define PE      128
#define GATES   512          // 4*PE
#define IN_DIM  33           // 1 + ACT
#define INV_SC  0.08838834764831843f   // 1/sqrt(128)

// LSTM smem cache: float4 e-slices of W_hh in shared memory (of 32); rest in regs
#define EC4 28

typedef unsigned long long u64t;
typedef unsigned int       u32t;

// ---------------- device scratch (static, no allocation) ----------------
__device__ __align__(16) float  g_XN [T_STEPS * OBS];      // normalized obs [t][j]
__device__ __align__(16) float  g_SH [T_STEPS * GATES];    // per-step gate constant [t][r]
__device__ __align__(16) float  g_W0 [GATES];              // W_ih[:,0]
__device__            float4 g_W4 [32 * GATES];            // W_hh e-sliced: [e][r] = W_hh[r][4e..4e+3]
__device__ __align__(16) float  g_q  [HID * MSG];          // q = pos @ Wq^T + bq, [i][m]
__device__ __align__(16) float  g_QWT[PE * HID];           // inv * (q @ Wk), TRANSPOSED: [p][i]
__device__ __align__(16) float  g_qbs[HID];                // inv * (q . bk)
__device__ __align__(16) float  g_HT [T_STEPS * PE * OBS]; // h storage TRANSPOSED: [t][p][j]

// ---------------- packed fp32x2 helpers (sm_100+) ----------------
__device__ __forceinline__ void ffma2(u64t& d, u64t a, u64t b) {
    asm("fma.rn.f32x2 %0, %1, %2, %0;" : "+l"(d) : "l"(a), "l"(b));
}
__device__ __forceinline__ u64t dup2(float x) {
    u64t r; asm("mov.b64 %0, {%1, %1};" : "=l"(r) : "f"(x)); return r;
}
__device__ __forceinline__ float hsum2(u64t v) {
    float lo, hi; asm("mov.b64 {%0, %1}, %2;" : "=f"(lo), "=f"(hi) : "l"(v));
    return lo + hi;
}
__device__ __forceinline__ void unpack2f(u64t v, float& lo, float& hi) {
    asm("mov.b64 {%0, %1}, %2;" : "=f"(lo), "=f"(hi) : "l"(v));
}

// ---------------- cp.async ----------------
__device__ __forceinline__ void cp16(u32t dst, const void* src) {
    asm volatile("cp.async.cg.shared.global [%0], [%1], 16;" :: "r"(dst), "l"(src));
}
__device__ __forceinline__ void cp_commit() {
    asm volatile("cp.async.commit_group;");
}

// ---------------- fast-but-accurate activations ----------------
__device__ __forceinline__ float sig_f(float x) {
    return __fdividef(1.f, 1.f + __expf(-x));
}
__device__ __forceinline__ float tanh_f(float x) {
    float ax = fabsf(x);
    float e  = __expf(-2.f * ax);       // in (0,1], never overflows
    float r  = __fdividef(1.f - e, 1.f + e);
    return copysignf(r, x);
}

// ======================================================================
// K0: normalized obs + per-step gate constants. grid(T_STEPS), block(512)
// ======================================================================
__global__ void k_pre1(const float* __restrict__ obs,
                       const float* __restrict__ act,
                       const float* __restrict__ shift,
                       const float* __restrict__ scale,
                       const float* __restrict__ W_ih,
                       const float* __restrict__ b_ih,
                       const float* __restrict__ b_hh) {
    __shared__ float actS[ACT];
    int t = blockIdx.x;
    int r = threadIdx.x;
    if (r < ACT) actS[r] = act[t * ACT + r];
    __syncthreads();

    g_XN[t * OBS + r] = (obs[t * OBS + r] - shift[r]) / (scale[r] + 1e-8f);

    float sh = b_ih[r] + b_hh[r];
    const float* wrow = W_ih + r * IN_DIM + 1;
#pragma unroll 8
    for (int a = 0; a < ACT; a++) sh = fmaf(wrow[a], actS[a], sh);
    g_SH[t * GATES + r] = sh;
}

// ======================================================================
// K0b: W_hh e-slice layout + W0. grid(32), block(512)
// ======================================================================
__global__ void k_pre2(const float* __restrict__ W_hh,
                       const float* __restrict__ W_ih) {
    int e = blockIdx.x;
    int r = threadIdx.x;
    const float* row = W_hh + r * PE + 4 * e;
    g_W4[e * GATES + r] = make_float4(row[0], row[1], row[2], row[3]);
    if (e == 0) g_W0[r] = W_ih[r * IN_DIM];
}

// ======================================================================
// K1: q = pos @ Wq^T + bq. grid(128) i-tiles of 8, block(256)
// dyn smem = 4KB posS + 64KB WqT = 69632 B
// ======================================================================
__global__ void __launch_bounds__(256) k_q(const float* __restrict__ pos,
                                           const float* __restrict__ Wq,
                                           const float* __restrict__ bq) {
    extern __shared__ float sm[];
    float* posS = sm;            // [8][128]
    float* WqT  = sm + 8 * PE;   // [e][m]
    int i0 = blockIdx.x * 8;
    int tid = threadIdx.x;

    for (int idx = tid; idx < 8 * PE; idx += 256) posS[idx] = pos[i0 * PE + idx];
    for (int idx = tid; idx < MSG * PE; idx += 256) {
        int mm = idx >> 7, e = idx & 127;
        WqT[e * MSG + mm] = Wq[idx];
    }
    __syncthreads();

    int m  = tid & 127;
    int ih = tid >> 7;
    float bqm = bq[m];
#pragma unroll
    for (int s = 0; s < 4; s++) {
        int isub = ih * 4 + s;
        float acc = bqm;
#pragma unroll 8
        for (int e = 0; e < PE; e++)
            acc = fmaf(posS[isub * PE + e], WqT[e * MSG + m], acc);
        g_q[(i0 + isub) * MSG + m] = acc;
    }
}

// ======================================================================
// K2: QWT[p][i] = inv*(q@Wk)[i][p]; qbs[i] = inv*q[i].bk
// grid(128) i-tiles of 8, block(256). dyn smem = 4KB qS + 64KB WkS
// ======================================================================
__global__ void __launch_bounds__(256) k_qw(const float* __restrict__ Wk,
                                            const float* __restrict__ bk) {
    extern __shared__ float sm[];
    float* qS  = sm;             // [8][128]
    float* WkS = sm + 8 * MSG;   // [m][p]
    int i0 = blockIdx.x * 8;
    int tid = threadIdx.x;

    for (int idx = tid; idx < 8 * MSG; idx += 256) qS[idx] = g_q[i0 * MSG + idx];
    for (int idx = tid; idx < MSG * PE; idx += 256) WkS[idx] = Wk[idx];
    __syncthreads();

    int p  = tid & 127;
    int ih = tid >> 7;
#pragma unroll
    for (int s = 0; s < 4; s++) {
        int isub = ih * 4 + s;
        float acc = 0.f;
#pragma unroll 8
        for (int m = 0; m < MSG; m++)
            acc = fmaf(qS[isub * MSG + m], WkS[m * PE + p], acc);
        g_QWT[p * HID + i0 + isub] = acc * INV_SC;
    }
    if (tid < 8) {
        float acc = 0.f;
#pragma unroll 8
        for (int m = 0; m < MSG; m++) acc = fmaf(qS[tid * MSG + m], bk[m], acc);
        g_qbs[i0 + tid] = acc * INV_SC;
    }
}

// ======================================================================
// K3: LSTM over 256 steps. 128 CTAs x 4 chains, 128 threads (thread = unit m).
// FFMA2 paired along the reduction dim (e-components): both operand pairs are
// naturally adjacent float4 halves -> zero packing movs.
// dyn smem: EC4 float4 e-slices of W_hh (224KB) + h state (2KB) = 231424 B.
// Remaining 4 slices live permanently in registers.
// ======================================================================
__global__ void __launch_bounds__(128, 1) k_lstm() {
    extern __shared__ float sm[];
    float4* Ws = reinterpret_cast<float4*>(sm);   // [EC4][512]
    float*  hs = sm + EC4 * GATES * 4;            // [4][128]

    int m  = threadIdx.x;
    int j0 = blockIdx.x * 4;

    for (int idx = m; idx < EC4 * GATES; idx += 128) Ws[idx] = g_W4[idx];
#pragma unroll
    for (int ch = 0; ch < 4; ch++) hs[ch * PE + m] = 0.f;

    // tail W slices (e = EC4..31) held in registers for the whole kernel
    ulonglong2 wr[32 - EC4][4];
#pragma unroll
    for (int e = 0; e < 32 - EC4; e++)
#pragma unroll
        for (int r = 0; r < 4; r++)
            wr[e][r] = *reinterpret_cast<const ulonglong2*>(
                &g_W4[(EC4 + e) * GATES + m + r * 128]);

    float cst[4] = {0.f, 0.f, 0.f, 0.f};
    float w00 = g_W0[m], w01 = g_W0[m + 128], w02 = g_W0[m + 256], w03 = g_W0[m + 384];
    __syncthreads();

    for (int t = 0; t < T_STEPS; t++) {
        float sh0 = g_SH[t * GATES + m];
        float sh1 = g_SH[t * GATES + m + 128];
        float sh2 = g_SH[t * GATES + m + 256];
        float sh3 = g_SH[t * GATES + m + 384];
        float xn[4];
#pragma unroll
        for (int ch = 0; ch < 4; ch++) xn[ch] = g_XN[t * OBS + j0 + ch];

        u64t acc2[4][4];   // [gate][ch], even-e lane + odd-e lane
#pragma unroll
        for (int r = 0; r < 4; r++)
#pragma unroll
            for (int ch = 0; ch < 4; ch++) acc2[r][ch] = 0ull;

#pragma unroll 4
        for (int e = 0; e < EC4; e++) {
            ulonglong2 wa = *reinterpret_cast<const ulonglong2*>(&Ws[e * GATES + m]);
            ulonglong2 wb = *reinterpret_cast<const ulonglong2*>(&Ws[e * GATES + m + 128]);
            ulonglong2 wc = *reinterpret_cast<const ulonglong2*>(&Ws[e * GATES + m + 256]);
            ulonglong2 wd = *reinterpret_cast<const ulonglong2*>(&Ws[e * GATES + m + 384]);
#pragma unroll
            for (int ch = 0; ch < 4; ch++) {
                ulonglong2 h2 = *reinterpret_cast<const ulonglong2*>(hs + ch * PE + e * 4);
                ffma2(acc2[0][ch], wa.x, h2.x); ffma2(acc2[0][ch], wa.y, h2.y);
                ffma2(acc2[1][ch], wb.x, h2.x); ffma2(acc2[1][ch], wb.y, h2.y);
                ffma2(acc2[2][ch], wc.x, h2.x); ffma2(acc2[2][ch], wc.y, h2.y);
                ffma2(acc2[3][ch], wd.x, h2.x); ffma2(acc2[3][ch], wd.y, h2.y);
            }
        }
        // register-resident tail slices
#pragma unroll
        for (int e = 0; e < 32 - EC4; e++) {
#pragma unroll
            for (int ch = 0; ch < 4; ch++) {
                ulonglong2 h2 = *reinterpret_cast<const ulonglong2*>(hs + ch * PE + (EC4 + e) * 4);
                ffma2(acc2[0][ch], wr[e][0].x, h2.x); ffma2(acc2[0][ch], wr[e][0].y, h2.y);
                ffma2(acc2[1][ch], wr[e][1].x, h2.x); ffma2(acc2[1][ch], wr[e][1].y, h2.y);
                ffma2(acc2[2][ch], wr[e][2].x, h2.x); ffma2(acc2[2][ch], wr[e][2].y, h2.y);
                ffma2(acc2[3][ch], wr[e][3].x, h2.x); ffma2(acc2[3][ch], wr[e][3].y, h2.y);
            }
        }

        __syncthreads();   // all reads of hs done before overwrite

        float hv[4];
#pragma unroll
        for (int ch = 0; ch < 4; ch++) {
            float gi = hsum2(acc2[0][ch]) + sh0 + w00 * xn[ch];
            float gf = hsum2(acc2[1][ch]) + sh1 + w01 * xn[ch];
            float gg = hsum2(acc2[2][ch]) + sh2 + w02 * xn[ch];
            float go = hsum2(acc2[3][ch]) + sh3 + w03 * xn[ch];
            float ig = sig_f(gi);
            float fg = sig_f(gf);
            float g  = tanh_f(gg);
            float og = sig_f(go);
            float cn = fmaf(fg, cst[ch], ig * g);
            cst[ch] = cn;
            hv[ch]  = og * tanh_f(cn);
            hs[ch * PE + m] = hv[ch];
        }
        *reinterpret_cast<float4*>(&g_HT[(t * PE + m) * OBS + j0]) =
            make_float4(hv[0], hv[1], hv[2], hv[3]);

        __syncthreads();   // writes visible before next step's reads
    }
}

// ======================================================================
// K4: attention readout, FFMA2 paired along j + cp.async double-buffered Bs.
// grid(8 i-tiles, 256 t), block(256).
// dyn smem: As 64KB + Bs0 64KB + Bs1 64KB + xn 2KB = 198656 B
// out[t][i] = tanh( sum_j tanh(QWT[:,i].H_t[:,j] + qbs[i]) * xn[t][j] )
// ======================================================================
__global__ void __launch_bounds__(256, 1) k_attn(float* __restrict__ out) {
    extern __shared__ float sm[];
    float* As  = sm;               // [p][i_local] 128x128
    float* Bs0 = sm + 16384;       // [p][j_local] 128x128 (buffer 0)
    float* Bs1 = sm + 32768;       // buffer 1
    float* xnS = sm + 49152;       // [512]

    int t   = blockIdx.y;
    int bx  = blockIdx.x;
    int tid = threadIdx.x;
    int tx  = tid & 15;            // j-group
    int ty  = tid >> 4;            // i-group

    const float* Hbase = g_HT + (size_t)t * PE * OBS;
    u32t b0s = (u32t)__cvta_generic_to_shared(Bs0);
    u32t b1s = (u32t)__cvta_generic_to_shared(Bs1);

    // prologue: As + xn plain loads; tile 0 via cp.async
    for (int idx = tid; idx < 4096; idx += 256) {
        int p = idx >> 5, c4 = idx & 31;
        reinterpret_cast<float4*>(As)[p * 32 + c4] =
            reinterpret_cast<const float4*>(g_QWT + p * HID + bx * 128)[c4];
    }
    for (int idx = tid; idx < OBS; idx += 256) xnS[idx] = g_XN[t * OBS + idx];
    for (int idx = tid; idx < 4096; idx += 256) {
        int p = idx >> 5, c4 = idx & 31;
        cp16(b0s + idx * 16, Hbase + p * OBS + c4 * 4);
    }
    cp_commit();

    float qb[8];
#pragma unroll
    for (int ii = 0; ii < 8; ii++) qb[ii] = g_qbs[bx * 128 + ty * 8 + ii];

    float outa[8];
#pragma unroll
    for (int ii = 0; ii < 8; ii++) outa[ii] = 0.f;

    for (int jt = 0; jt < 4; jt++) {
        // issue next tile into the other buffer (its last readers synced at jt-1)
        if (jt < 3) {
            u32t dsts = ((jt + 1) & 1) ? b1s : b0s;
            for (int idx = tid; idx < 4096; idx += 256) {
                int p = idx >> 5, c4 = idx & 31;
                cp16(dsts + idx * 16, Hbase + p * OBS + (jt + 1) * 128 + c4 * 4);
            }
            cp_commit();
            asm volatile("cp.async.wait_group 1;");
        } else {
            asm volatile("cp.async.wait_group 0;");
        }
        __syncthreads();

        const float* Bs = (jt & 1) ? Bs1 : Bs0;

        u64t acc2[8][4];   // [ii][j-pair]
#pragma unroll
        for (int ii = 0; ii < 8; ii++)
#pragma unroll
            for (int jp = 0; jp < 4; jp++) acc2[ii][jp] = 0ull;

#pragma unroll 4
        for (int p = 0; p < PE; p++) {
            float4 a0 = *reinterpret_cast<const float4*>(As + p * 128 + ty * 8);
            float4 a1 = *reinterpret_cast<const float4*>(As + p * 128 + ty * 8 + 4);
            ulonglong2 b0 = *reinterpret_cast<const ulonglong2*>(Bs + p * 128 + tx * 8);
            ulonglong2 b1 = *reinterpret_cast<const ulonglong2*>(Bs + p * 128 + tx * 8 + 4);
            u64t ad[8];
            ad[0] = dup2(a0.x); ad[1] = dup2(a0.y); ad[2] = dup2(a0.z); ad[3] = dup2(a0.w);
            ad[4] = dup2(a1.x); ad[5] = dup2(a1.y); ad[6] = dup2(a1.z); ad[7] = dup2(a1.w);
#pragma unroll
            for (int ii = 0; ii < 8; ii++) {
                ffma2(acc2[ii][0], ad[ii], b0.x);
                ffma2(acc2[ii][1], ad[ii], b0.y);
                ffma2(acc2[ii][2], ad[ii], b1.x);
                ffma2(acc2[ii][3], ad[ii], b1.y);
            }
        }

        float xr[8];
#pragma unroll
        for (int jj = 0; jj < 8; jj++) xr[jj] = xnS[jt * 128 + tx * 8 + jj];
#pragma unroll
        for (int ii = 0; ii < 8; ii++) {
#pragma unroll
            for (int jp = 0; jp < 4; jp++) {
                float lo, hi;
                unpack2f(acc2[ii][jp], lo, hi);
                outa[ii] = fmaf(tanh_f(lo + qb[ii]), xr[jp * 2 + 0], outa[ii]);
                outa[ii] = fmaf(tanh_f(hi + qb[ii]), xr[jp * 2 + 1], outa[ii]);
            }
        }
        __syncthreads();   // compute done before next issue overwrites buffer
    }

    // cross-tx reduction via smem (reuse As)
#pragma unroll
    for (int ii = 0; ii < 8; ii++) As[(ty * 8 + ii) * 16 + tx] = outa[ii];
    __syncthreads();

    if (tid < 128) {
        float s = 0.f;
#pragma unroll
        for (int q = 0; q < 16; q++) s += As[tid * 16 + q];
        out[t * HID + bx * 128 + tid] = tanh_f(s);
    }
}

// ======================================================================
// launcher
// ======================================================================
extern "C" void kernel_launch(void* const* d_in, const int* in_sizes, int n_in,
                              void* d_out, int out_size) {
    const float* obs    = (const float*)d_in[0];   // (256,512)
    const float* pact   = (const float*)d_in[1];   // (256,32)
    const float* shift  = (const float*)d_in[2];   // (512,)
    const float* scale  = (const float*)d_in[3];   // (512,)
    const float* pos    = (const float*)d_in[4];   // (1024,128)
    const float* W_ih   = (const float*)d_in[5];   // (512,33)
    const float* b_ih   = (const float*)d_in[6];   // (512,)
    const float* W_hh   = (const float*)d_in[7];   // (512,128)
    const float* b_hh   = (const float*)d_in[8];   // (512,)
    const float* Wq     = (const float*)d_in[9];   // (128,128)
    const float* bq     = (const float*)d_in[10];  // (128,)
    const float* Wk     = (const float*)d_in[11];  // (128,128)
    const float* bk     = (const float*)d_in[12];  // (128,)
    float* out = (float*)d_out;                    // (256,1024)

    cudaFuncSetAttribute(k_q,    cudaFuncAttributeMaxDynamicSharedMemorySize, 69632);
    cudaFuncSetAttribute(k_qw,   cudaFuncAttributeMaxDynamicSharedMemorySize, 69632);
    cudaFuncSetAttribute(k_lstm, cudaFuncAttributeMaxDynamicSharedMemorySize, 231424);
    cudaFuncSetAttribute(k_attn, cudaFuncAttributeMaxDynamicSharedMemorySize, 198656);

    k_pre1<<<T_STEPS, 512>>>(obs, pact, shift, scale, W_ih, b_ih, b_hh);
    k_pre2<<<32, 512>>>(W_hh, W_ih);
    k_q  <<<128, 256, 69632>>>(pos, Wq, bq);
    k_qw <<<128, 256, 69632>>>(Wk, bk);
    k_lstm<<<128, 128, 231424>>>();
    k_attn<<<dim3(8, T_STEPS), 256, 198656>>>(out);
}

// round 13
// speedup vs baseline: 1.6697x; 1.5274x over previous
#include <cuda_runtime.h>
#include <cuda_bf16.h>
#include <cstdint>
#include <math.h>

// Problem dims
#define T_STEPS 256
#define OBS     512
#define ACT     32
#define HID     1024
#define MSG     128
#define PE      128
#define GATES   512          // 4*PE
#define IN_DIM  33           // 1 + ACT
#define INV_SC  0.08838834764831843f   // 1/sqrt(128)

// LSTM smem cache: float4 e-slices of W_hh in shared memory (of 32); rest in regs
#define EC4 28

typedef unsigned long long u64t;
typedef unsigned int       u32t;

// ---------------- device scratch (static, no allocation) ----------------
__device__ __align__(16) float  g_XN [T_STEPS * OBS];      // normalized obs [t][j]
__device__ __align__(16) float  g_SH [T_STEPS * GATES];    // per-step gate constant [t][r]
__device__ __align__(16) float  g_W0 [GATES];              // W_ih[:,0]
__device__            float4 g_W4 [32 * GATES];            // W_hh e-sliced
__device__ __align__(16) float  g_q  [HID * MSG];          // q = pos @ Wq^T + bq, [i][m]
__device__ __align__(16) float  g_QWT[PE * HID];           // inv * (q @ Wk), [p][i]
__device__ __align__(16) float  g_qbs[HID];                // inv * (q . bk)
// bf16 split operands for the tensor-core attention GEMM
__device__ __align__(256) __nv_bfloat16 g_QAh[HID * PE];   // A hi: [i][p]
__device__ __align__(256) __nv_bfloat16 g_QAl[HID * PE];   // A lo: [i][p]
__device__ __align__(256) __nv_bfloat16 g_HBh[(size_t)T_STEPS * OBS * PE]; // B hi: [t][j][p]
__device__ __align__(256) __nv_bfloat16 g_HBl[(size_t)T_STEPS * OBS * PE]; // B lo: [t][j][p]

// ---------------- packed fp32x2 helpers (k_lstm) ----------------
__device__ __forceinline__ void ffma2(u64t& d, u64t a, u64t b) {
    asm("fma.rn.f32x2 %0, %1, %2, %0;" : "+l"(d) : "l"(a), "l"(b));
}
__device__ __forceinline__ float hsum2(u64t v) {
    float lo, hi; asm("mov.b64 {%0, %1}, %2;" : "=f"(lo), "=f"(hi) : "l"(v));
    return lo + hi;
}

// ---------------- cp.async ----------------
__device__ __forceinline__ void cp16(u32t dst, const void* src) {
    asm volatile("cp.async.cg.shared.global [%0], [%1], 16;" :: "r"(dst), "l"(src));
}
__device__ __forceinline__ void cp_commit() {
    asm volatile("cp.async.commit_group;");
}
__device__ __forceinline__ void cp_wait0() {
    asm volatile("cp.async.wait_group 0;" ::: "memory");
}

// ---------------- ldmatrix / mma.sync (sm_80 baseline, ptxas-safe) ----------------
#define LDSM4(r, addr) \
    asm volatile("ldmatrix.sync.aligned.m8n8.x4.shared.b16 {%0,%1,%2,%3}, [%4];" \
        : "=r"((r)[0]), "=r"((r)[1]), "=r"((r)[2]), "=r"((r)[3]) : "r"(addr))

__device__ __forceinline__ void mma_bf16(float* d, const u32t* a, u32t b0, u32t b1) {
    asm volatile(
        "mma.sync.aligned.m16n8k16.row.col.f32.bf16.bf16.f32 "
        "{%0,%1,%2,%3}, {%4,%5,%6,%7}, {%8,%9}, {%0,%1,%2,%3};"
        : "+f"(d[0]), "+f"(d[1]), "+f"(d[2]), "+f"(d[3])
        : "r"(a[0]), "r"(a[1]), "r"(a[2]), "r"(a[3]), "r"(b0), "r"(b1));
}

// ---------------- fast-but-accurate activations ----------------
__device__ __forceinline__ float sig_f(float x) {
    return __fdividef(1.f, 1.f + __expf(-x));
}
__device__ __forceinline__ float tanh_f(float x) {
    float ax = fabsf(x);
    float e  = __expf(-2.f * ax);
    float r  = __fdividef(1.f - e, 1.f + e);
    return copysignf(r, x);
}

// ======================================================================
// K0: normalized obs + per-step gate constants. grid(T_STEPS), block(512)
// ======================================================================
__global__ void k_pre1(const float* __restrict__ obs,
                       const float* __restrict__ act,
                       const float* __restrict__ shift,
                       const float* __restrict__ scale,
                       const float* __restrict__ W_ih,
                       const float* __restrict__ b_ih,
                       const float* __restrict__ b_hh) {
    __shared__ float actS[ACT];
    int t = blockIdx.x;
    int r = threadIdx.x;
    if (r < ACT) actS[r] = act[t * ACT + r];
    __syncthreads();

    g_XN[t * OBS + r] = (obs[t * OBS + r] - shift[r]) / (scale[r] + 1e-8f);

    float sh = b_ih[r] + b_hh[r];
    const float* wrow = W_ih + r * IN_DIM + 1;
#pragma unroll 8
    for (int a = 0; a < ACT; a++) sh = fmaf(wrow[a], actS[a], sh);
    g_SH[t * GATES + r] = sh;
}

// ======================================================================
// K0b: W_hh e-slice layout + W0. grid(32), block(512)
// ======================================================================
__global__ void k_pre2(const float* __restrict__ W_hh,
                       const float* __restrict__ W_ih) {
    int e = blockIdx.x;
    int r = threadIdx.x;
    const float* row = W_hh + r * PE + 4 * e;
    g_W4[e * GATES + r] = make_float4(row[0], row[1], row[2], row[3]);
    if (e == 0) g_W0[r] = W_ih[r * IN_DIM];
}

// ======================================================================
// K1: q = pos @ Wq^T + bq. grid(128) i-tiles of 8, block(256)
// ======================================================================
__global__ void __launch_bounds__(256) k_q(const float* __restrict__ pos,
                                           const float* __restrict__ Wq,
                                           const float* __restrict__ bq) {
    extern __shared__ float sm[];
    float* posS = sm;            // [8][128]
    float* WqT  = sm + 8 * PE;   // [e][m]
    int i0 = blockIdx.x * 8;
    int tid = threadIdx.x;

    for (int idx = tid; idx < 8 * PE; idx += 256) posS[idx] = pos[i0 * PE + idx];
    for (int idx = tid; idx < MSG * PE; idx += 256) {
        int mm = idx >> 7, e = idx & 127;
        WqT[e * MSG + mm] = Wq[idx];
    }
    __syncthreads();

    int m  = tid & 127;
    int ih = tid >> 7;
    float bqm = bq[m];
#pragma unroll
    for (int s = 0; s < 4; s++) {
        int isub = ih * 4 + s;
        float acc = bqm;
#pragma unroll 8
        for (int e = 0; e < PE; e++)
            acc = fmaf(posS[isub * PE + e], WqT[e * MSG + m], acc);
        g_q[(i0 + isub) * MSG + m] = acc;
    }
}

// ======================================================================
// K2: QWT[p][i] = inv*(q@Wk)[i][p]; qbs[i] = inv*q[i].bk
// ======================================================================
__global__ void __launch_bounds__(256) k_qw(const float* __restrict__ Wk,
                                            const float* __restrict__ bk) {
    extern __shared__ float sm[];
    float* qS  = sm;             // [8][128]
    float* WkS = sm + 8 * MSG;   // [m][p]
    int i0 = blockIdx.x * 8;
    int tid = threadIdx.x;

    for (int idx = tid; idx < 8 * MSG; idx += 256) qS[idx] = g_q[i0 * MSG + idx];
    for (int idx = tid; idx < MSG * PE; idx += 256) WkS[idx] = Wk[idx];
    __syncthreads();

    int p  = tid & 127;
    int ih = tid >> 7;
#pragma unroll
    for (int s = 0; s < 4; s++) {
        int isub = ih * 4 + s;
        float acc = 0.f;
#pragma unroll 8
        for (int m = 0; m < MSG; m++)
            acc = fmaf(qS[isub * MSG + m], WkS[m * PE + p], acc);
        g_QWT[p * HID + i0 + isub] = acc * INV_SC;
    }
    if (tid < 8) {
        float acc = 0.f;
#pragma unroll 8
        for (int m = 0; m < MSG; m++) acc = fmaf(qS[tid * MSG + m], bk[m], acc);
        g_qbs[i0 + tid] = acc * INV_SC;
    }
}

// ======================================================================
// K2b: split QWT into bf16 hi/lo, layout [i][p]. grid(128), block(256)
// ======================================================================
__global__ void k_split() {
#pragma unroll
    for (int k = 0; k < 4; k++) {
        int idx = blockIdx.x * 1024 + k * 256 + threadIdx.x;   // 0..131071
        int i = idx >> 7, p = idx & 127;
        float v = g_QWT[p * HID + i];
        __nv_bfloat16 bh = __float2bfloat16(v);
        float rem = v - __bfloat162float(bh);
        g_QAh[idx] = bh;
        g_QAl[idx] = __float2bfloat16(rem);
    }
}

// ======================================================================
// K3: LSTM over 256 steps; stores h as bf16 hi/lo in [t][j][p]
// ======================================================================
__global__ void __launch_bounds__(128, 1) k_lstm() {
    extern __shared__ float sm[];
    float4* Ws = reinterpret_cast<float4*>(sm);   // [EC4][512]
    float*  hs = sm + EC4 * GATES * 4;            // [4][128]

    int m  = threadIdx.x;
    int j0 = blockIdx.x * 4;

    for (int idx = m; idx < EC4 * GATES; idx += 128) Ws[idx] = g_W4[idx];
#pragma unroll
    for (int ch = 0; ch < 4; ch++) hs[ch * PE + m] = 0.f;

    ulonglong2 wr[32 - EC4][4];
#pragma unroll
    for (int e = 0; e < 32 - EC4; e++)
#pragma unroll
        for (int r = 0; r < 4; r++)
            wr[e][r] = *reinterpret_cast<const ulonglong2*>(
                &g_W4[(EC4 + e) * GATES + m + r * 128]);

    float cst[4] = {0.f, 0.f, 0.f, 0.f};
    float w00 = g_W0[m], w01 = g_W0[m + 128], w02 = g_W0[m + 256], w03 = g_W0[m + 384];
    __syncthreads();

    for (int t = 0; t < T_STEPS; t++) {
        float sh0 = g_SH[t * GATES + m];
        float sh1 = g_SH[t * GATES + m + 128];
        float sh2 = g_SH[t * GATES + m + 256];
        float sh3 = g_SH[t * GATES + m + 384];
        float xn[4];
#pragma unroll
        for (int ch = 0; ch < 4; ch++) xn[ch] = g_XN[t * OBS + j0 + ch];

        u64t acc2[4][4];
#pragma unroll
        for (int r = 0; r < 4; r++)
#pragma unroll
            for (int ch = 0; ch < 4; ch++) acc2[r][ch] = 0ull;

#pragma unroll 4
        for (int e = 0; e < EC4; e++) {
            ulonglong2 wa = *reinterpret_cast<const ulonglong2*>(&Ws[e * GATES + m]);
            ulonglong2 wb = *reinterpret_cast<const ulonglong2*>(&Ws[e * GATES + m + 128]);
            ulonglong2 wc = *reinterpret_cast<const ulonglong2*>(&Ws[e * GATES + m + 256]);
            ulonglong2 wd = *reinterpret_cast<const ulonglong2*>(&Ws[e * GATES + m + 384]);
#pragma unroll
            for (int ch = 0; ch < 4; ch++) {
                ulonglong2 h2 = *reinterpret_cast<const ulonglong2*>(hs + ch * PE + e * 4);
                ffma2(acc2[0][ch], wa.x, h2.x); ffma2(acc2[0][ch], wa.y, h2.y);
                ffma2(acc2[1][ch], wb.x, h2.x); ffma2(acc2[1][ch], wb.y, h2.y);
                ffma2(acc2[2][ch], wc.x, h2.x); ffma2(acc2[2][ch], wc.y, h2.y);
                ffma2(acc2[3][ch], wd.x, h2.x); ffma2(acc2[3][ch], wd.y, h2.y);
            }
        }
#pragma unroll
        for (int e = 0; e < 32 - EC4; e++) {
#pragma unroll
            for (int ch = 0; ch < 4; ch++) {
                ulonglong2 h2 = *reinterpret_cast<const ulonglong2*>(hs + ch * PE + (EC4 + e) * 4);
                ffma2(acc2[0][ch], wr[e][0].x, h2.x); ffma2(acc2[0][ch], wr[e][0].y, h2.y);
                ffma2(acc2[1][ch], wr[e][1].x, h2.x); ffma2(acc2[1][ch], wr[e][1].y, h2.y);
                ffma2(acc2[2][ch], wr[e][2].x, h2.x); ffma2(acc2[2][ch], wr[e][2].y, h2.y);
                ffma2(acc2[3][ch], wr[e][3].x, h2.x); ffma2(acc2[3][ch], wr[e][3].y, h2.y);
            }
        }

        __syncthreads();

#pragma unroll
        for (int ch = 0; ch < 4; ch++) {
            float gi = hsum2(acc2[0][ch]) + sh0 + w00 * xn[ch];
            float gf = hsum2(acc2[1][ch]) + sh1 + w01 * xn[ch];
            float gg = hsum2(acc2[2][ch]) + sh2 + w02 * xn[ch];
            float go = hsum2(acc2[3][ch]) + sh3 + w03 * xn[ch];
            float ig = sig_f(gi);
            float fg = sig_f(gf);
            float g  = tanh_f(gg);
            float og = sig_f(go);
            float cn = fmaf(fg, cst[ch], ig * g);
            cst[ch] = cn;
            float hv = og * tanh_f(cn);
            hs[ch * PE + m] = hv;
            __nv_bfloat16 bh = __float2bfloat16(hv);
            float rem = hv - __bfloat162float(bh);
            size_t base = ((size_t)t * OBS + j0 + ch) * PE + m;
            g_HBh[base] = bh;
            g_HBl[base] = __float2bfloat16(rem);
        }
        __syncthreads();
    }
}

// ======================================================================
// K4: attention via warp-level mma.sync bf16 (split-bf16, 3-term compensated).
// grid(8 i-tiles, 256 t), block(256) = 8 warps; warp w owns i-rows 16w..16w+15.
// smem (bf16 tiles padded to 136 elems/row = 272B -> conflict-free ldmatrix):
//   Ah @0       (34816 B)     Al @34816
//   B buffers: Bh0 @69632, Bl0 @104448, Bh1 @139264, Bl1 @174080
//   xn  @208896 (2048 B)      red @210944 (512 B)   -> total 211456
// ======================================================================
#define PADE 136
#define PADB 272
#define TILE_BYTES 34816
#define SM_AH  0u
#define SM_AL  34816u
#define SM_B0H 69632u
#define SM_B0L 104448u
#define SM_B1H 139264u
#define SM_B1L 174080u
#define SM_XN  208896u
#define SM_RED 210944u
#define SM_ATTN_TOTAL 211456

__global__ void __launch_bounds__(256, 1) k_attn(float* __restrict__ out) {
    extern __shared__ char smc[];
    u32t smb = (u32t)__cvta_generic_to_shared(smc);
    float* xnS  = reinterpret_cast<float*>(smc + SM_XN);
    float* redS = reinterpret_cast<float*>(smc + SM_RED);

    int tid  = threadIdx.x;
    int w    = tid >> 5;       // warp 0..7
    int lane = tid & 31;
    int t  = blockIdx.y;
    int i0 = blockIdx.x * 128;

    const __nv_bfloat16* Hh = g_HBh + (size_t)t * OBS * PE;
    const __nv_bfloat16* Hl = g_HBl + (size_t)t * OBS * PE;

    // ---- prologue: A (hi+lo) + B tile 0 (hi+lo) via cp.async; xn plain ----
    for (int idx = tid; idx < 2048; idx += 256) {
        int row = idx >> 4, c = idx & 15;
        u32t doff = (u32t)(row * PADB + c * 16);
        const __nv_bfloat16* sa = g_QAh + (size_t)(i0 + row) * PE + c * 8;
        const __nv_bfloat16* sl = g_QAl + (size_t)(i0 + row) * PE + c * 8;
        cp16(smb + SM_AH + doff, sa);
        cp16(smb + SM_AL + doff, sl);
        cp16(smb + SM_B0H + doff, Hh + (size_t)row * PE + c * 8);
        cp16(smb + SM_B0L + doff, Hl + (size_t)row * PE + c * 8);
    }
    cp_commit();
    for (int idx = tid; idx < OBS; idx += 256) xnS[idx] = g_XN[t * OBS + idx];

    // ldmatrix per-lane base offsets
    int grp = lane >> 3, lr = lane & 7;
    // A: lanes 0-7 tile(row0-7,col0-7); 8-15 (row8-15,col0-7); 16-23 (row0-7,col8-15); 24-31 (row8-15,col8-15)
    u32t a_off = (u32t)((16 * w + (grp & 1) * 8 + lr) * PADB + (grp >> 1) * 16);
    // B: lanes 0-7 (n0-7,k0-7); 8-15 (n0-7,k8-15); 16-23 (n8-15,k0-7); 24-31 (n8-15,k8-15)
    u32t b_off = (u32t)(((grp >> 1) * 8 + lr) * PADB + (grp & 1) * 16);

    float qb0 = g_qbs[i0 + 16 * w + (lane >> 2)];
    float qb1 = g_qbs[i0 + 16 * w + (lane >> 2) + 8];
    float outa0 = 0.f, outa1 = 0.f;

    for (int jt = 0; jt < 4; jt++) {
        cp_wait0();
        __syncthreads();
        // prefetch B tile jt+1 into the other buffer
        if (jt < 3) {
            u32t dbh = ((jt + 1) & 1) ? SM_B1H : SM_B0H;
            u32t dbl = ((jt + 1) & 1) ? SM_B1L : SM_B0L;
            for (int idx = tid; idx < 2048; idx += 256) {
                int row = idx >> 4, c = idx & 15;
                u32t doff = (u32t)(row * PADB + c * 16);
                size_t src = (size_t)((jt + 1) * 128 + row) * PE + c * 8;
                cp16(smb + dbh + doff, Hh + src);
                cp16(smb + dbl + doff, Hl + src);
            }
            cp_commit();
        }

        u32t bhb = smb + ((jt & 1) ? SM_B1H : SM_B0H) + b_off;
        u32t blb = smb + ((jt & 1) ? SM_B1L : SM_B0L) + b_off;
        u32t ahb = smb + SM_AH + a_off;
        u32t alb = smb + SM_AL + a_off;

        float d[16][4];
#pragma unroll
        for (int nt = 0; nt < 16; nt++)
#pragma unroll
            for (int q = 0; q < 4; q++) d[nt][q] = 0.f;

        for (int ks = 0; ks < 8; ks++) {
            u32t ah[4], al[4];
            LDSM4(ah, ahb + ks * 32);
            LDSM4(al, alb + ks * 32);
#pragma unroll
            for (int ntp = 0; ntp < 8; ntp++) {
                u32t bh[4], bl[4];
                LDSM4(bh, bhb + ntp * (16 * PADB) + ks * 32);
                LDSM4(bl, blb + ntp * (16 * PADB) + ks * 32);
                mma_bf16(d[2 * ntp],     ah, bh[0], bh[1]);
                mma_bf16(d[2 * ntp],     ah, bl[0], bl[1]);
                mma_bf16(d[2 * ntp],     al, bh[0], bh[1]);
                mma_bf16(d[2 * ntp + 1], ah, bh[2], bh[3]);
                mma_bf16(d[2 * ntp + 1], ah, bl[2], bl[3]);
                mma_bf16(d[2 * ntp + 1], al, bh[2], bh[3]);
            }
        }

        // epilogue: w = tanh(d + qb); outa += w * xn[j]
#pragma unroll
        for (int nt = 0; nt < 16; nt++) {
            float2 xr = *reinterpret_cast<const float2*>(
                xnS + jt * 128 + nt * 8 + (lane & 3) * 2);
            outa0 = fmaf(tanh_f(d[nt][0] + qb0), xr.x, outa0);
            outa0 = fmaf(tanh_f(d[nt][1] + qb0), xr.y, outa0);
            outa1 = fmaf(tanh_f(d[nt][2] + qb1), xr.x, outa1);
            outa1 = fmaf(tanh_f(d[nt][3] + qb1), xr.y, outa1);
        }
    }

    // quad reduce (lanes sharing a row are consecutive l%4 groups)
#pragma unroll
    for (int m = 1; m <= 2; m <<= 1) {
        outa0 += __shfl_xor_sync(0xFFFFFFFFu, outa0, m);
        outa1 += __shfl_xor_sync(0xFFFFFFFFu, outa1, m);
    }
    __syncthreads();   // done reading B buffers / xn before redS reuse is fine (separate region)
    if ((lane & 3) == 0) {
        redS[16 * w + (lane >> 2)]     = outa0;
        redS[16 * w + (lane >> 2) + 8] = outa1;
    }
    __syncthreads();
    if (tid < 128)
        out[t * HID + i0 + tid] = tanh_f(redS[tid]);
}

// ======================================================================
// launcher
// ======================================================================
extern "C" void kernel_launch(void* const* d_in, const int* in_sizes, int n_in,
                              void* d_out, int out_size) {
    const float* obs    = (const float*)d_in[0];   // (256,512)
    const float* pact   = (const float*)d_in[1];   // (256,32)
    const float* shift  = (const float*)d_in[2];   // (512,)
    const float* scale  = (const float*)d_in[3];   // (512,)
    const float* pos    = (const float*)d_in[4];   // (1024,128)
    const float* W_ih   = (const float*)d_in[5];   // (512,33)
    const float* b_ih   = (const float*)d_in[6];   // (512,)
    const float* W_hh   = (const float*)d_in[7];   // (512,128)
    const float* b_hh   = (const float*)d_in[8];   // (512,)
    const float* Wq     = (const float*)d_in[9];   // (128,128)
    const float* bq     = (const float*)d_in[10];  // (128,)
    const float* Wk     = (const float*)d_in[11];  // (128,128)
    const float* bk     = (const float*)d_in[12];  // (128,)
    float* out = (float*)d_out;                    // (256,1024)

    cudaFuncSetAttribute(k_q,    cudaFuncAttributeMaxDynamicSharedMemorySize, 69632);
    cudaFuncSetAttribute(k_qw,   cudaFuncAttributeMaxDynamicSharedMemorySize, 69632);
    cudaFuncSetAttribute(k_lstm, cudaFuncAttributeMaxDynamicSharedMemorySize, 231424);
    cudaFuncSetAttribute(k_attn, cudaFuncAttributeMaxDynamicSharedMemorySize, SM_ATTN_TOTAL);

    k_pre1<<<T_STEPS, 512>>>(obs, pact, shift, scale, W_ih, b_ih, b_hh);
    k_pre2<<<32, 512>>>(W_hh, W_ih);
    k_q   <<<128, 256, 69632>>>(pos, Wq, bq);
    k_lstm<<<128, 128, 231424>>>();
    k_qw  <<<128, 256, 69632>>>(Wk, bk);
    k_split<<<128, 256>>>();
    k_attn<<<dim3(8, T_STEPS), 256, SM_ATTN_TOTAL>>>(out);
}

// round 15
// speedup vs baseline: 2.2258x; 1.3330x over previous
#include <cuda_runtime.h>
#include <cuda_bf16.h>
#include <cstdint>
#include <math.h>

// Problem dims
#define T_STEPS 256
#define OBS     512
#define ACT     32
#define HID     1024
#define MSG     128
#define PE      128
#define GATES   512          // 4*PE
#define IN_DIM  33           // 1 + ACT
#define INV_SC  0.08838834764831843f   // 1/sqrt(128)

typedef unsigned long long u64t;
typedef unsigned int       u32t;

// ---------------- device scratch (static, no allocation) ----------------
__device__ __align__(16) float  g_XN [T_STEPS * OBS];      // normalized obs [t][j]
__device__ __align__(16) float  g_SH [T_STEPS * GATES];    // per-step gate constant [t][r]
__device__ __align__(16) float  g_W0 [GATES];              // W_ih[:,0]
__device__ __align__(16) float  g_q  [HID * MSG];          // q = pos @ Wq^T + bq, [i][m]
__device__ __align__(16) float  g_QWT[PE * HID];           // inv * (q @ Wk), [p][i]
__device__ __align__(16) float  g_qbs[HID];                // inv * (q . bk)
// W_hh bf16 hi/lo in mma a-fragment layout: [tile(mt*8+kt)][lane][q] packed bf16x2
__device__ __align__(16) u32t g_WAh[256 * 128];
__device__ __align__(16) u32t g_WAl[256 * 128];
// bf16 split operands for the tensor-core attention GEMM
__device__ __align__(256) __nv_bfloat16 g_QAh[HID * PE];   // A hi: [i][p]
__device__ __align__(256) __nv_bfloat16 g_QAl[HID * PE];   // A lo: [i][p]
__device__ __align__(256) __nv_bfloat16 g_HBh[(size_t)T_STEPS * OBS * PE]; // B hi: [t][j][p]
__device__ __align__(256) __nv_bfloat16 g_HBl[(size_t)T_STEPS * OBS * PE]; // B lo: [t][j][p]

// ---------------- cp.async ----------------
__device__ __forceinline__ void cp16(u32t dst, const void* src) {
    asm volatile("cp.async.cg.shared.global [%0], [%1], 16;" :: "r"(dst), "l"(src));
}
__device__ __forceinline__ void cp_commit() {
    asm volatile("cp.async.commit_group;");
}
__device__ __forceinline__ void cp_wait0() {
    asm volatile("cp.async.wait_group 0;" ::: "memory");
}

// ---------------- ldmatrix / mma.sync (sm_80 baseline, ptxas-safe) ----------------
#define LDSM4(r, addr) \
    asm volatile("ldmatrix.sync.aligned.m8n8.x4.shared.b16 {%0,%1,%2,%3}, [%4];" \
        : "=r"((r)[0]), "=r"((r)[1]), "=r"((r)[2]), "=r"((r)[3]) : "r"(addr))

__device__ __forceinline__ void mma_bf16(float* d, const u32t* a, u32t b0, u32t b1) {
    asm volatile(
        "mma.sync.aligned.m16n8k16.row.col.f32.bf16.bf16.f32 "
        "{%0,%1,%2,%3}, {%4,%5,%6,%7}, {%8,%9}, {%0,%1,%2,%3};"
        : "+f"(d[0]), "+f"(d[1]), "+f"(d[2]), "+f"(d[3])
        : "r"(a[0]), "r"(a[1]), "r"(a[2]), "r"(a[3]), "r"(b0), "r"(b1));
}

// ---------------- fast-but-accurate activations ----------------
__device__ __forceinline__ float sig_f(float x) {
    return __fdividef(1.f, 1.f + __expf(-x));
}
__device__ __forceinline__ float tanh_f(float x) {
    float ax = fabsf(x);
    float e  = __expf(-2.f * ax);
    float r  = __fdividef(1.f - e, 1.f + e);
    return copysignf(r, x);
}

// ======================================================================
// K0: normalized obs + per-step gate constants (+W0 once). grid(T_STEPS), block(512)
// ======================================================================
__global__ void k_pre1(const float* __restrict__ obs,
                       const float* __restrict__ act,
                       const float* __restrict__ shift,
                       const float* __restrict__ scale,
                       const float* __restrict__ W_ih,
                       const float* __restrict__ b_ih,
                       const float* __restrict__ b_hh) {
    __shared__ float actS[ACT];
    int t = blockIdx.x;
    int r = threadIdx.x;
    if (r < ACT) actS[r] = act[t * ACT + r];
    __syncthreads();

    g_XN[t * OBS + r] = (obs[t * OBS + r] - shift[r]) / (scale[r] + 1e-8f);
    if (t == 0) g_W0[r] = W_ih[r * IN_DIM];

    float sh = b_ih[r] + b_hh[r];
    const float* wrow = W_ih + r * IN_DIM + 1;
#pragma unroll 8
    for (int a = 0; a < ACT; a++) sh = fmaf(wrow[a], actS[a], sh);
    g_SH[t * GATES + r] = sh;
}

// ======================================================================
// K0b: W_hh -> bf16 hi/lo a-fragment layout. grid(256 tiles), block(128)
// tile = mt*8+kt ; thread = lane*4+q ; q -> (dr,dc) = ((q&1)*8, (q>>1)*8)
// a-frag element (r,c): r = mt*16 + lane/4 + dr ; c = kt*16 + (lane%4)*2 + dc
// ======================================================================
__global__ void k_prew(const float* __restrict__ W_hh) {
    int tile = blockIdx.x;
    int l = threadIdx.x >> 2;
    int q = threadIdx.x & 3;
    int mt = tile >> 3, kt = tile & 7;
    int r = mt * 16 + (l >> 2) + (q & 1) * 8;
    int c = kt * 16 + (l & 3) * 2 + (q >> 1) * 8;
    float v0 = W_hh[r * PE + c], v1 = W_hh[r * PE + c + 1];
    __nv_bfloat16 h0 = __float2bfloat16(v0), h1 = __float2bfloat16(v1);
    float r0 = v0 - __bfloat162float(h0), r1 = v1 - __bfloat162float(h1);
    __nv_bfloat16 e0 = __float2bfloat16(r0), e1 = __float2bfloat16(r1);
    u32t hi = (u32t)__bfloat16_as_ushort(h0) | ((u32t)__bfloat16_as_ushort(h1) << 16);
    u32t lo = (u32t)__bfloat16_as_ushort(e0) | ((u32t)__bfloat16_as_ushort(e1) << 16);
    g_WAh[tile * 128 + l * 4 + q] = hi;
    g_WAl[tile * 128 + l * 4 + q] = lo;
}

// ======================================================================
// K1: q = pos @ Wq^T + bq. grid(128) i-tiles of 8, block(256)
// ======================================================================
__global__ void __launch_bounds__(256) k_q(const float* __restrict__ pos,
                                           const float* __restrict__ Wq,
                                           const float* __restrict__ bq) {
    extern __shared__ float sm[];
    float* posS = sm;            // [8][128]
    float* WqT  = sm + 8 * PE;   // [e][m]
    int i0 = blockIdx.x * 8;
    int tid = threadIdx.x;

    for (int idx = tid; idx < 8 * PE; idx += 256) posS[idx] = pos[i0 * PE + idx];
    for (int idx = tid; idx < MSG * PE; idx += 256) {
        int mm = idx >> 7, e = idx & 127;
        WqT[e * MSG + mm] = Wq[idx];
    }
    __syncthreads();

    int m  = tid & 127;
    int ih = tid >> 7;
    float bqm = bq[m];
#pragma unroll
    for (int s = 0; s < 4; s++) {
        int isub = ih * 4 + s;
        float acc = bqm;
#pragma unroll 8
        for (int e = 0; e < PE; e++)
            acc = fmaf(posS[isub * PE + e], WqT[e * MSG + m], acc);
        g_q[(i0 + isub) * MSG + m] = acc;
    }
}

// ======================================================================
// K2: QWT[p][i] = inv*(q@Wk)[i][p]; qbs[i] = inv*q[i].bk
// ======================================================================
__global__ void __launch_bounds__(256) k_qw(const float* __restrict__ Wk,
                                            const float* __restrict__ bk) {
    extern __shared__ float sm[];
    float* qS  = sm;             // [8][128]
    float* WkS = sm + 8 * MSG;   // [m][p]
    int i0 = blockIdx.x * 8;
    int tid = threadIdx.x;

    for (int idx = tid; idx < 8 * MSG; idx += 256) qS[idx] = g_q[i0 * MSG + idx];
    for (int idx = tid; idx < MSG * PE; idx += 256) WkS[idx] = Wk[idx];
    __syncthreads();

    int p  = tid & 127;
    int ih = tid >> 7;
#pragma unroll
    for (int s = 0; s < 4; s++) {
        int isub = ih * 4 + s;
        float acc = 0.f;
#pragma unroll 8
        for (int m = 0; m < MSG; m++)
            acc = fmaf(qS[isub * MSG + m], WkS[m * PE + p], acc);
        g_QWT[p * HID + i0 + isub] = acc * INV_SC;
    }
    if (tid < 8) {
        float acc = 0.f;
#pragma unroll 8
        for (int m = 0; m < MSG; m++) acc = fmaf(qS[tid * MSG + m], bk[m], acc);
        g_qbs[i0 + tid] = acc * INV_SC;
    }
}

// ======================================================================
// K2b: split QWT into bf16 hi/lo, layout [i][p]. grid(128), block(256)
// ======================================================================
__global__ void k_split() {
#pragma unroll
    for (int k = 0; k < 4; k++) {
        int idx = blockIdx.x * 1024 + k * 256 + threadIdx.x;   // 0..131071
        int i = idx >> 7, p = idx & 127;
        float v = g_QWT[p * HID + i];
        __nv_bfloat16 bh = __float2bfloat16(v);
        float rem = v - __bfloat162float(bh);
        g_QAh[idx] = bh;
        g_QAl[idx] = __float2bfloat16(rem);
    }
}

// ======================================================================
// K3: tensor-core LSTM. 128 CTAs x 4 chains, 256 threads (8 warps).
// Warp w owns gate rows 64w..64w+63 (m-tiles 4w..4w+3).
// Wh a-frags in registers (128 regs/thread), Wl a-frags in smem (128KB).
// h stored per step in smem [n(pad 8)][k=128] bf16, ROW STRIDE 272 BYTES
// (256 data + 16 pad; 4n-bank shift per row -> conflict-free b-frag LDS.32).
// 3-term compensated bf16 mma: Wh@hh + Wh@hl + Wl@hh.
// smem: [0,131072) Wl frags ; [131072,+2176) hb_h ; [133248,+2176) hb_l ;
//       [135424,+8192) gate dump  -> total 143616
// ======================================================================
#define LS_WL  0
#define LS_HH  131072
#define LS_HL  133248
#define LS_GS  135424
#define LS_TOT 143616
#define HSTR   272          // bytes per n-row of h buffers (128 bf16 + 8 pad)

__global__ void __launch_bounds__(256, 1) k_lstm_tc() {
    extern __shared__ char smc[];
    uint4* wlS = reinterpret_cast<uint4*>(smc + LS_WL);
    float* gsm = reinterpret_cast<float*>(smc + LS_GS);

    int tid = threadIdx.x, w = tid >> 5, l = tid & 31;
    int m = tid & 127, chp = tid >> 7;     // activation identity
    int j0 = blockIdx.x * 4;

    // stage Wl frag table (128KB) + zero both h buffers (2*2176 B = 1088 u32)
    const uint4* gWl4 = reinterpret_cast<const uint4*>(g_WAl);
    for (int i = tid; i < 8192; i += 256) wlS[i] = gWl4[i];
    for (int i = tid; i < 1088; i += 256)
        reinterpret_cast<u32t*>(smc + LS_HH)[i] = 0u;

    // Wh a-frags -> registers (32 uint4 = 128 regs)
    uint4 wh[32];
    {
        const uint4* gWh4 = reinterpret_cast<const uint4*>(g_WAh);
#pragma unroll
        for (int i = 0; i < 4; i++)
#pragma unroll
            for (int kt = 0; kt < 8; kt++)
                wh[i * 8 + kt] = gWh4[(((w * 4 + i) * 8) + kt) * 32 + l];
    }
    float w0r[4];
#pragma unroll
    for (int g = 0; g < 4; g++) w0r[g] = g_W0[g * 128 + m];
    float cst[2] = {0.f, 0.f};

    // per-lane b-frag base byte offsets: n = l/4, k-byte = (l%4)*4
    const char* bh_base = smc + LS_HH + (l >> 2) * HSTR + (l & 3) * 4;
    const char* bl_base = smc + LS_HL + (l >> 2) * HSTR + (l & 3) * 4;

    __syncthreads();

    for (int t = 0; t < T_STEPS; t++) {
        float shv[4];
#pragma unroll
        for (int g = 0; g < 4; g++) shv[g] = g_SH[t * GATES + g * 128 + m];
        float2 xn2 = *reinterpret_cast<const float2*>(g_XN + t * OBS + j0 + 2 * chp);

        float d[4][4];
#pragma unroll
        for (int i = 0; i < 4; i++) { d[i][0] = d[i][1] = d[i][2] = d[i][3] = 0.f; }

#pragma unroll
        for (int kt = 0; kt < 8; kt++) {
            u32t bh0 = *reinterpret_cast<const u32t*>(bh_base + kt * 32);
            u32t bh1 = *reinterpret_cast<const u32t*>(bh_base + kt * 32 + 16);
            u32t bl0 = *reinterpret_cast<const u32t*>(bl_base + kt * 32);
            u32t bl1 = *reinterpret_cast<const u32t*>(bl_base + kt * 32 + 16);
#pragma unroll
            for (int i = 0; i < 4; i++) {
                uint4 alv = wlS[(((w * 4 + i) * 8) + kt) * 32 + l];
                u32t a[4]  = {wh[i * 8 + kt].x, wh[i * 8 + kt].y,
                              wh[i * 8 + kt].z, wh[i * 8 + kt].w};
                u32t al[4] = {alv.x, alv.y, alv.z, alv.w};
                mma_bf16(d[i], a,  bh0, bh1);   // Wh @ hh
                mma_bf16(d[i], a,  bl0, bl1);   // Wh @ hl
                mma_bf16(d[i], al, bh0, bh1);   // Wl @ hh
            }
        }

        // dump D -> gsm[r][4] (lanes whose cols are the 4 real chains)
        if ((l & 3) < 2) {
            int cc = (l & 3) * 2;
#pragma unroll
            for (int i = 0; i < 4; i++) {
                int r = 64 * w + 16 * i + (l >> 2);
                *reinterpret_cast<float2*>(gsm + r * 4 + cc)       = make_float2(d[i][0], d[i][1]);
                *reinterpret_cast<float2*>(gsm + (r + 8) * 4 + cc) = make_float2(d[i][2], d[i][3]);
            }
        }
        __syncthreads();

        // activations: thread (m, chains 2chp, 2chp+1)
        float2 gv0 = *reinterpret_cast<const float2*>(gsm + (0 * 128 + m) * 4 + 2 * chp);
        float2 gv1 = *reinterpret_cast<const float2*>(gsm + (1 * 128 + m) * 4 + 2 * chp);
        float2 gv2 = *reinterpret_cast<const float2*>(gsm + (2 * 128 + m) * 4 + 2 * chp);
        float2 gv3 = *reinterpret_cast<const float2*>(gsm + (3 * 128 + m) * 4 + 2 * chp);
#pragma unroll
        for (int c2 = 0; c2 < 2; c2++) {
            float xnc = c2 ? xn2.y : xn2.x;
            float gi = (c2 ? gv0.y : gv0.x) + shv[0] + w0r[0] * xnc;
            float gf = (c2 ? gv1.y : gv1.x) + shv[1] + w0r[1] * xnc;
            float gg = (c2 ? gv2.y : gv2.x) + shv[2] + w0r[2] * xnc;
            float go = (c2 ? gv3.y : gv3.x) + shv[3] + w0r[3] * xnc;
            float ig = sig_f(gi), fg = sig_f(gf), g = tanh_f(gg), og = sig_f(go);
            float cn = fmaf(fg, cst[c2], ig * g);
            cst[c2] = cn;
            float hv = og * tanh_f(cn);
            __nv_bfloat16 bh = __float2bfloat16(hv);
            float rem = hv - __bfloat162float(bh);
            __nv_bfloat16 bl = __float2bfloat16(rem);
            int ch = 2 * chp + c2;
            *reinterpret_cast<__nv_bfloat16*>(smc + LS_HH + ch * HSTR + m * 2) = bh;
            *reinterpret_cast<__nv_bfloat16*>(smc + LS_HL + ch * HSTR + m * 2) = bl;
            size_t gb = ((size_t)t * OBS + j0 + ch) * PE + m;
            g_HBh[gb] = bh;
            g_HBl[gb] = bl;
        }
        __syncthreads();
    }
}

// ======================================================================
// K4: attention via warp-level mma.sync bf16 (unchanged from R13-pass).
// grid(8 i-tiles, 256 t), block(256) = 8 warps; warp w owns i-rows 16w..16w+15.
// ======================================================================
#define PADB 272
#define SM_AH  0u
#define SM_AL  34816u
#define SM_B0H 69632u
#define SM_B0L 104448u
#define SM_B1H 139264u
#define SM_B1L 174080u
#define SM_XN  208896u
#define SM_RED 210944u
#define SM_ATTN_TOTAL 211456

__global__ void __launch_bounds__(256, 1) k_attn(float* __restrict__ out) {
    extern __shared__ char smc[];
    u32t smb = (u32t)__cvta_generic_to_shared(smc);
    float* xnS  = reinterpret_cast<float*>(smc + SM_XN);
    float* redS = reinterpret_cast<float*>(smc + SM_RED);

    int tid  = threadIdx.x;
    int w    = tid >> 5;
    int lane = tid & 31;
    int t  = blockIdx.y;
    int i0 = blockIdx.x * 128;

    const __nv_bfloat16* Hh = g_HBh + (size_t)t * OBS * PE;
    const __nv_bfloat16* Hl = g_HBl + (size_t)t * OBS * PE;

    for (int idx = tid; idx < 2048; idx += 256) {
        int row = idx >> 4, c = idx & 15;
        u32t doff = (u32t)(row * PADB + c * 16);
        cp16(smb + SM_AH + doff, g_QAh + (size_t)(i0 + row) * PE + c * 8);
        cp16(smb + SM_AL + doff, g_QAl + (size_t)(i0 + row) * PE + c * 8);
        cp16(smb + SM_B0H + doff, Hh + (size_t)row * PE + c * 8);
        cp16(smb + SM_B0L + doff, Hl + (size_t)row * PE + c * 8);
    }
    cp_commit();
    for (int idx = tid; idx < OBS; idx += 256) xnS[idx] = g_XN[t * OBS + idx];

    int grp = lane >> 3, lr = lane & 7;
    u32t a_off = (u32t)((16 * w + (grp & 1) * 8 + lr) * PADB + (grp >> 1) * 16);
    u32t b_off = (u32t)(((grp >> 1) * 8 + lr) * PADB + (grp & 1) * 16);

    float qb0 = g_qbs[i0 + 16 * w + (lane >> 2)];
    float qb1 = g_qbs[i0 + 16 * w + (lane >> 2) + 8];
    float outa0 = 0.f, outa1 = 0.f;

    for (int jt = 0; jt < 4; jt++) {
        cp_wait0();
        __syncthreads();
        if (jt < 3) {
            u32t dbh = ((jt + 1) & 1) ? SM_B1H : SM_B0H;
            u32t dbl = ((jt + 1) & 1) ? SM_B1L : SM_B0L;
            for (int idx = tid; idx < 2048; idx += 256) {
                int row = idx >> 4, c = idx & 15;
                u32t doff = (u32t)(row * PADB + c * 16);
                size_t src = (size_t)((jt + 1) * 128 + row) * PE + c * 8;
                cp16(smb + dbh + doff, Hh + src);
                cp16(smb + dbl + doff, Hl + src);
            }
            cp_commit();
        }

        u32t bhb = smb + ((jt & 1) ? SM_B1H : SM_B0H) + b_off;
        u32t blb = smb + ((jt & 1) ? SM_B1L : SM_B0L) + b_off;
        u32t ahb = smb + SM_AH + a_off;
        u32t alb = smb + SM_AL + a_off;

        float d[16][4];
#pragma unroll
        for (int nt = 0; nt < 16; nt++)
#pragma unroll
            for (int q = 0; q < 4; q++) d[nt][q] = 0.f;

        for (int ks = 0; ks < 8; ks++) {
            u32t ah[4], al[4];
            LDSM4(ah, ahb + ks * 32);
            LDSM4(al, alb + ks * 32);
#pragma unroll
            for (int ntp = 0; ntp < 8; ntp++) {
                u32t bh[4], bl[4];
                LDSM4(bh, bhb + ntp * (16 * PADB) + ks * 32);
                LDSM4(bl, blb + ntp * (16 * PADB) + ks * 32);
                mma_bf16(d[2 * ntp],     ah, bh[0], bh[1]);
                mma_bf16(d[2 * ntp],     ah, bl[0], bl[1]);
                mma_bf16(d[2 * ntp],     al, bh[0], bh[1]);
                mma_bf16(d[2 * ntp + 1], ah, bh[2], bh[3]);
                mma_bf16(d[2 * ntp + 1], ah, bl[2], bl[3]);
                mma_bf16(d[2 * ntp + 1], al, bh[2], bh[3]);
            }
        }

#pragma unroll
        for (int nt = 0; nt < 16; nt++) {
            float2 xr = *reinterpret_cast<const float2*>(
                xnS + jt * 128 + nt * 8 + (lane & 3) * 2);
            outa0 = fmaf(tanh_f(d[nt][0] + qb0), xr.x, outa0);
            outa0 = fmaf(tanh_f(d[nt][1] + qb0), xr.y, outa0);
            outa1 = fmaf(tanh_f(d[nt][2] + qb1), xr.x, outa1);
            outa1 = fmaf(tanh_f(d[nt][3] + qb1), xr.y, outa1);
        }
    }

#pragma unroll
    for (int mm = 1; mm <= 2; mm <<= 1) {
        outa0 += __shfl_xor_sync(0xFFFFFFFFu, outa0, mm);
        outa1 += __shfl_xor_sync(0xFFFFFFFFu, outa1, mm);
    }
    __syncthreads();
    if ((lane & 3) == 0) {
        redS[16 * w + (lane >> 2)]     = outa0;
        redS[16 * w + (lane >> 2) + 8] = outa1;
    }
    __syncthreads();
    if (tid < 128)
        out[t * HID + i0 + tid] = tanh_f(redS[tid]);
}

// ======================================================================
// launcher
// ======================================================================
extern "C" void kernel_launch(void* const* d_in, const int* in_sizes, int n_in,
                              void* d_out, int out_size) {
    const float* obs    = (const float*)d_in[0];   // (256,512)
    const float* pact   = (const float*)d_in[1];   // (256,32)
    const float* shift  = (const float*)d_in[2];   // (512,)
    const float* scale  = (const float*)d_in[3];   // (512,)
    const float* pos    = (const float*)d_in[4];   // (1024,128)
    const float* W_ih   = (const float*)d_in[5];   // (512,33)
    const float* b_ih   = (const float*)d_in[6];   // (512,)
    const float* W_hh   = (const float*)d_in[7];   // (512,128)
    const float* b_hh   = (const float*)d_in[8];   // (512,)
    const float* Wq     = (const float*)d_in[9];   // (128,128)
    const float* bq     = (const float*)d_in[10];  // (128,)
    const float* Wk     = (const float*)d_in[11];  // (128,128)
    const float* bk     = (const float*)d_in[12];  // (128,)
    float* out = (float*)d_out;                    // (256,1024)

    cudaFuncSetAttribute(k_q,       cudaFuncAttributeMaxDynamicSharedMemorySize, 69632);
    cudaFuncSetAttribute(k_qw,      cudaFuncAttributeMaxDynamicSharedMemorySize, 69632);
    cudaFuncSetAttribute(k_lstm_tc, cudaFuncAttributeMaxDynamicSharedMemorySize, LS_TOT);
    cudaFuncSetAttribute(k_attn,    cudaFuncAttributeMaxDynamicSharedMemorySize, SM_ATTN_TOTAL);

    k_pre1<<<T_STEPS, 512>>>(obs, pact, shift, scale, W_ih, b_ih, b_hh);
    k_prew<<<256, 128>>>(W_hh);
    k_q   <<<128, 256, 69632>>>(pos, Wq, bq);
    k_lstm_tc<<<128, 256, LS_TOT>>>();
    k_qw  <<<128, 256, 69632>>>(Wk, bk);
    k_split<<<128, 256>>>();
    k_attn<<<dim3(8, T_STEPS), 256, SM_ATTN_TOTAL>>>(out);
}